// round 1
// baseline (speedup 1.0000x reference)
#include <cuda_runtime.h>

#define IMW 512
#define IMH 512
#define NIMG 48          // B*C = 16*3
#define TSZ 32

// Scratch (static __device__ — no allocations allowed)
__device__ float g_tmp[NIMG*IMH*IMW];
__device__ float g_imc[NIMG*IMH*IMW];
__device__ float g_tn [NIMG*TSZ*TSZ];

// ---------------------------------------------------------------------------
// K0: template normalize: tn = (t - mean(t)) / ||t - mean(t)||  per (b,c)
// ---------------------------------------------------------------------------
__global__ void k_tnorm(const float* __restrict__ t) {
    __shared__ float red[256];
    int img = blockIdx.x;
    int tid = threadIdx.x;
    const float4* tp = (const float4*)(t + img * 1024);
    float4 v = tp[tid];                     // 256 threads x 4 = 1024 elems
    red[tid] = v.x + v.y + v.z + v.w;
    __syncthreads();
    for (int o = 128; o > 0; o >>= 1) {
        if (tid < o) red[tid] += red[tid + o];
        __syncthreads();
    }
    float mean = red[0] * (1.0f / 1024.0f);
    __syncthreads();
    float cx = v.x - mean, cy = v.y - mean, cz = v.z - mean, cw = v.w - mean;
    red[tid] = cx*cx + cy*cy + cz*cz + cw*cw;
    __syncthreads();
    for (int o = 128; o > 0; o >>= 1) {
        if (tid < o) red[tid] += red[tid + o];
        __syncthreads();
    }
    float inv = 1.0f / sqrtf(red[0]);
    float4* outp = (float4*)(g_tn + img * 1024);
    outp[tid] = make_float4(cx*inv, cy*inv, cz*inv, cw*inv);
}

// ---------------------------------------------------------------------------
// K1/K3: horizontal 32-wide box sum (offsets -15..+16), zero padded.
// SQ=0: input = im;  SQ=1: input = g_imc, squared on load.  Output: g_tmp.
// One block = 8 rows, smem row padded with 16 zeros each side.
// ---------------------------------------------------------------------------
template<int SQ>
__global__ __launch_bounds__(256) void k_hbox(const float* __restrict__ im) {
    __shared__ float s[8][544];
    int tid = threadIdx.x;
    int row0 = blockIdx.x * 8;                 // global row index (img*512 + y)
    const float* src = SQ ? (const float*)g_imc : im;

    // zero pads: cols [0..15] and [528..543]
    {
        int r = tid >> 5, c = tid & 31;
        s[r][(c < 16) ? c : (512 + c)] = 0.0f;
    }
    for (int i = tid; i < 8 * 512; i += 256) {
        int r = i >> 9, c = i & 511;
        float v = src[(row0 + r) * IMW + c];
        if (SQ) v *= v;
        s[r][16 + c] = v;
    }
    __syncthreads();

    int w = tid >> 5, lane = tid & 31;
    float* orow = g_tmp + (row0 + w) * IMW;
    #pragma unroll 4
    for (int c = 0; c < 16; c++) {
        int x = c * 32 + lane;
        float sum = 0.0f;
        #pragma unroll
        for (int j = 0; j < 32; j++) sum += s[w][x + 1 + j];  // = x-15+j (+16 pad)
        orow[x] = sum;
    }
}

// ---------------------------------------------------------------------------
// K2/K4: vertical 32-tall box sum of g_tmp (running sum per column segment).
// FINAL=0: g_imc = im - S1/1024
// FINAL=1: g_imc = g_imc / sqrt(max(S2, 0))   (in place)
// 4 segments of 128 rows per column for parallelism. Coalesced across x.
// ---------------------------------------------------------------------------
template<int FINAL>
__global__ __launch_bounds__(256) void k_vbox(const float* __restrict__ im) {
    int idx = blockIdx.x * 256 + threadIdx.x;      // NIMG*IMW*4 threads
    int x   = idx % IMW;
    int img = (idx / IMW) % NIMG;
    int seg = idx / (IMW * NIMG);
    int y0  = seg * 128;

    const float* col = g_tmp + img * IMH * IMW + x;
    float s = 0.0f;
    #pragma unroll
    for (int j = y0 - 16; j < y0 + 16; j++)
        if (j >= 0) s += col[j * IMW];             // j < 512 always here

    const float* base = (FINAL ? (const float*)g_imc : im) + img * IMH * IMW + x;
    float* outp = g_imc + img * IMH * IMW + x;

    for (int y = y0; y < y0 + 128; y++) {
        if (y + 16 < IMH) s += col[(y + 16) * IMW];
        if (y - 16 >= 0)  s -= col[(y - 16) * IMW];
        float v = base[y * IMW];
        outp[y * IMW] = FINAL ? v / sqrtf(fmaxf(s, 0.0f))
                              : v - s * (1.0f / 1024.0f);
    }
}

// ---------------------------------------------------------------------------
// K5: direct 32x32 correlation: out[y,x] = sum a[y+u-15, x+v-15] * tn[u,v]
// Tile: 64(x) x 32(y) outputs / block of 256 threads.
// Mapping: lane -> output row (stride-100 smem rows => bank = 4*lane mod 32,
// conflict-free LDS.128 per quarter-warp), warp -> 8-wide x octet.
// Per thread: 8 outputs, 40-float register window per template row.
// ---------------------------------------------------------------------------
#define CTX 64
#define CTY 32
#define INROWS 63          // CTY + 31
#define INCOLS 95          // CTX + 31
#define INS 100            // smem row stride (mod 32 == 4 -> conflict-free)

__global__ __launch_bounds__(256) void k_conv(float* __restrict__ out) {
    __shared__ __align__(16) float s_in[INROWS * INS];
    __shared__ __align__(16) float s_t[TSZ * TSZ];

    int img = blockIdx.z;
    int X0 = blockIdx.x * CTX;
    int Y0 = blockIdx.y * CTY;
    int tid = threadIdx.x;

    // template tile
    ((float4*)s_t)[tid] = ((const float4*)(g_tn + img * 1024))[tid];

    // input tile rows [Y0-15, Y0+47], cols [X0-15, X0+79], zero outside
    const float* A = g_imc + img * IMH * IMW;
    for (int i = tid; i < INROWS * INCOLS; i += 256) {
        int ly = i / INCOLS, lx = i % INCOLS;
        int gy = Y0 - 15 + ly, gx = X0 - 15 + lx;
        float v = 0.0f;
        if (gy >= 0 && gy < IMH && gx >= 0 && gx < IMW) v = A[gy * IMW + gx];
        s_in[ly * INS + lx] = v;
    }
    __syncthreads();

    int r  = tid & 31;          // output row in tile
    int ox = (tid >> 5) * 8;    // output x octet base

    float acc[8];
    #pragma unroll
    for (int k = 0; k < 8; k++) acc[k] = 0.0f;

    #pragma unroll 1
    for (int u = 0; u < 32; u++) {
        float w[40];
        const float4* base = (const float4*)&s_in[(r + u) * INS + ox];
        #pragma unroll
        for (int k = 0; k < 10; k++) ((float4*)w)[k] = base[k];

        const float4* trow = (const float4*)&s_t[u * 32];
        #pragma unroll
        for (int v4 = 0; v4 < 8; v4++) {
            float4 t4 = trow[v4];
            float tv[4];
            tv[0] = t4.x; tv[1] = t4.y; tv[2] = t4.z; tv[3] = t4.w;
            #pragma unroll
            for (int dv = 0; dv < 4; dv++) {
                #pragma unroll
                for (int dx = 0; dx < 8; dx++)
                    acc[dx] = fmaf(w[4 * v4 + dv + dx], tv[dv], acc[dx]);
            }
        }
    }

    float* o = out + ((size_t)(img * IMH + Y0 + r)) * IMW + X0 + ox;
    ((float4*)o)[0] = make_float4(acc[0], acc[1], acc[2], acc[3]);
    ((float4*)o)[1] = make_float4(acc[4], acc[5], acc[6], acc[7]);
}

// ---------------------------------------------------------------------------
extern "C" void kernel_launch(void* const* d_in, const int* in_sizes, int n_in,
                              void* d_out, int out_size) {
    const float* im   = (const float*)d_in[0];  // (16,3,512,512) f32
    const float* tmpl = (const float*)d_in[1];  // (16,3,32,32)  f32
    float* out = (float*)d_out;                 // (16,3,512,512) f32

    k_tnorm<<<NIMG, 256>>>(tmpl);
    k_hbox<0><<<NIMG * IMH / 8, 256>>>(im);                 // S1 horizontal
    k_vbox<0><<<NIMG * IMW * 4 / 256, 256>>>(im);           // im_c
    k_hbox<1><<<NIMG * IMH / 8, 256>>>(im);                 // S2 horizontal (imc^2)
    k_vbox<1><<<NIMG * IMW * 4 / 256, 256>>>(im);           // a = imc/energy
    k_conv<<<dim3(IMW / CTX, IMH / CTY, NIMG), 256>>>(out); // correlation
}

// round 2
// speedup vs baseline: 1.0024x; 1.0024x over previous
#include <cuda_runtime.h>

#define IMW 512
#define IMH 512
#define NIMG 48          // B*C = 16*3
#define TSZ 32

// Scratch (static __device__ — no allocations allowed)
__device__ float g_tmp[NIMG*IMH*IMW];
__device__ float g_imc[NIMG*IMH*IMW];
__device__ float g_tn [NIMG*TSZ*TSZ];

__device__ __forceinline__ void ffma2(unsigned long long& d,
                                      unsigned long long a,
                                      unsigned long long b) {
    asm("fma.rn.f32x2 %0, %1, %2, %0;" : "+l"(d) : "l"(a), "l"(b));
}

// ---------------------------------------------------------------------------
// K0: template normalize: tn = (t - mean(t)) / ||t - mean(t)||  per (b,c)
// ---------------------------------------------------------------------------
__global__ void k_tnorm(const float* __restrict__ t) {
    __shared__ float red[256];
    int img = blockIdx.x;
    int tid = threadIdx.x;
    const float4* tp = (const float4*)(t + img * 1024);
    float4 v = tp[tid];
    red[tid] = v.x + v.y + v.z + v.w;
    __syncthreads();
    for (int o = 128; o > 0; o >>= 1) {
        if (tid < o) red[tid] += red[tid + o];
        __syncthreads();
    }
    float mean = red[0] * (1.0f / 1024.0f);
    __syncthreads();
    float cx = v.x - mean, cy = v.y - mean, cz = v.z - mean, cw = v.w - mean;
    red[tid] = cx*cx + cy*cy + cz*cz + cw*cw;
    __syncthreads();
    for (int o = 128; o > 0; o >>= 1) {
        if (tid < o) red[tid] += red[tid + o];
        __syncthreads();
    }
    float inv = 1.0f / sqrtf(red[0]);
    float4* outp = (float4*)(g_tn + img * 1024);
    outp[tid] = make_float4(cx*inv, cy*inv, cz*inv, cw*inv);
}

// ---------------------------------------------------------------------------
// K1/K3: horizontal 32-wide box sum (offsets -15..+16), zero padded.
// Running-sum version. Padded smem addressing HP(c)=c+c/16 so the 16-wide
// per-lane chunks map to distinct banks (stride 17, gcd(17,32)=1).
// ---------------------------------------------------------------------------
#define HP(c) ((c) + ((c) >> 4))

template<int SQ>
__global__ __launch_bounds__(256) void k_hbox(const float* __restrict__ im) {
    __shared__ float s [8][578];   // HP(543)=576 max
    __shared__ float so[8][544];   // HP(511)=542 max
    int tid = threadIdx.x;
    int row0 = blockIdx.x * 8;
    const float* src = SQ ? (const float*)g_imc : im;

    // fill padded rows: col c holds image col c-16, zero outside
    for (int i = tid; i < 8 * 544; i += 256) {
        int r = i / 544, c = i % 544;
        float v = 0.0f;
        if (c >= 16 && c < 528) {
            v = src[(row0 + r) * IMW + (c - 16)];
            if (SQ) v *= v;
        }
        s[r][HP(c)] = v;
    }
    __syncthreads();

    int w = tid >> 5, lane = tid & 31;
    int x0 = lane * 16;
    // window for output x: smem cols x+1 .. x+32
    float sum = 0.0f;
    #pragma unroll
    for (int j = 0; j < 32; j++) sum += s[w][HP(x0 + 1 + j)];
    so[w][HP(x0)] = sum;
    #pragma unroll
    for (int i = 1; i < 16; i++) {
        sum += s[w][HP(x0 + 32 + i)] - s[w][HP(x0 + i)];
        so[w][HP(x0 + i)] = sum;
    }
    __syncthreads();

    for (int i = tid; i < 8 * 512; i += 256) {
        int r = i >> 9, c = i & 511;
        g_tmp[(row0 + r) * IMW + c] = so[r][HP(c)];
    }
}

// ---------------------------------------------------------------------------
// K2/K4: vertical 32-tall box sum of g_tmp (running sum per column segment).
// FINAL=0: g_imc = im - S1/1024
// FINAL=1: g_imc = g_imc / sqrt(max(S2, 0))   (in place)
// ---------------------------------------------------------------------------
template<int FINAL>
__global__ __launch_bounds__(256) void k_vbox(const float* __restrict__ im) {
    int idx = blockIdx.x * 256 + threadIdx.x;
    int x   = idx % IMW;
    int img = (idx / IMW) % NIMG;
    int seg = idx / (IMW * NIMG);
    int y0  = seg * 128;

    const float* col = g_tmp + img * IMH * IMW + x;
    float s = 0.0f;
    #pragma unroll
    for (int j = y0 - 16; j < y0 + 16; j++)
        if (j >= 0) s += col[j * IMW];

    const float* base = (FINAL ? (const float*)g_imc : im) + img * IMH * IMW + x;
    float* outp = g_imc + img * IMH * IMW + x;

    for (int y = y0; y < y0 + 128; y++) {
        if (y + 16 < IMH) s += col[(y + 16) * IMW];
        if (y - 16 >= 0)  s -= col[(y - 16) * IMW];
        float v = base[y * IMW];
        outp[y * IMW] = FINAL ? v / sqrtf(fmaxf(s, 0.0f))
                              : v - s * (1.0f / 1024.0f);
    }
}

// ---------------------------------------------------------------------------
// K5: direct 32x32 correlation via packed f32x2 FMA.
// out[y,x] = sum_{u,v} a[y+u-15, x+v-15] * tn[u,v]
// Per thread: 8 outputs (octet along x), packed accumulators accP[dx] where
// final acc[dx] = lo+hi of the pair. w pairs always even-aligned (from
// LDS.128); template precomputed in both alignments:
//   tE[k] = (t[2k],   t[2k+1])   k=0..15   (even dx)
//   tO[i] = (t[2i-1], t[2i])     i=0..16   (odd dx, zero-padded edges)
// even dx=2d:   accP += wE[k+d]  x tE[k],  k=0..15
// odd  dx=2d+1: accP += wE[i+d]  x tO[i],  i=0..16
// ---------------------------------------------------------------------------
#define CTX 64
#define CTY 32
#define INROWS 63          // CTY + 31
#define INCOLS 95          // CTX + 31
#define INS 100            // smem row stride (400B, 16B-aligned, bank-skewed)

__global__ __launch_bounds__(256) void k_conv(float* __restrict__ out) {
    __shared__ __align__(16) float s_in[INROWS * INS];   // 25200 B
    __shared__ __align__(16) float s_tE[32 * 32];        // 4096 B
    __shared__ __align__(16) float s_tO[32 * 36];        // 4608 B (stride 18 u64)

    int img = blockIdx.z;
    int X0 = blockIdx.x * CTX;
    int Y0 = blockIdx.y * CTY;
    int tid = threadIdx.x;

    const float* T = g_tn + img * 1024;
    ((float4*)s_tE)[tid] = ((const float4*)T)[tid];
    for (int e = tid; e < 32 * 17; e += 256) {
        int u = e / 17, i = e % 17;
        float lo = (i == 0)  ? 0.0f : T[u * 32 + 2 * i - 1];
        float hi = (i == 16) ? 0.0f : T[u * 32 + 2 * i];
        s_tO[u * 36 + 2 * i]     = lo;
        s_tO[u * 36 + 2 * i + 1] = hi;
    }

    // input tile rows [Y0-15, Y0+47], cols [X0-15, X0+79]; zero-fill ALL of
    // the INS-wide row (packed path multiplies pad cols by 0 — must not be NaN)
    const float* A = g_imc + img * IMH * IMW;
    for (int i = tid; i < INROWS * INS; i += 256) {
        int ly = i / INS, lx = i % INS;
        int gy = Y0 - 15 + ly, gx = X0 - 15 + lx;
        float v = 0.0f;
        if (lx < INCOLS && gy >= 0 && gy < IMH && gx >= 0 && gx < IMW)
            v = A[gy * IMW + gx];
        s_in[i] = v;
    }
    __syncthreads();

    int r  = tid & 31;          // output row in tile
    int ox = (tid >> 5) * 8;    // output x octet base

    unsigned long long accP[8];
    #pragma unroll
    for (int k = 0; k < 8; k++) accP[k] = 0ull;   // (+0.f, +0.f)

    #pragma unroll 1
    for (int u = 0; u < 32; u++) {
        // 20 even-aligned w pairs covering w[0..39]
        const ulonglong2* wb = (const ulonglong2*)&s_in[(r + u) * INS + ox];
        unsigned long long wE[20];
        #pragma unroll
        for (int k = 0; k < 10; k++) {
            ulonglong2 q = wb[k];
            wE[2 * k] = q.x; wE[2 * k + 1] = q.y;
        }

        // even dx
        const ulonglong2* te = (const ulonglong2*)&s_tE[u * 32];
        #pragma unroll
        for (int k2 = 0; k2 < 8; k2++) {
            ulonglong2 tq = te[k2];
            #pragma unroll
            for (int d = 0; d < 4; d++) {
                ffma2(accP[2 * d], wE[2 * k2 + d],     tq.x);
                ffma2(accP[2 * d], wE[2 * k2 + 1 + d], tq.y);
            }
        }

        // odd dx
        const ulonglong2* to = (const ulonglong2*)&s_tO[u * 36];
        #pragma unroll
        for (int j2 = 0; j2 < 8; j2++) {
            ulonglong2 tq = to[j2];
            #pragma unroll
            for (int d = 0; d < 4; d++) {
                ffma2(accP[2 * d + 1], wE[2 * j2 + d],     tq.x);
                ffma2(accP[2 * d + 1], wE[2 * j2 + 1 + d], tq.y);
            }
        }
        unsigned long long tql = ((const unsigned long long*)&s_tO[u * 36])[16];
        #pragma unroll
        for (int d = 0; d < 4; d++)
            ffma2(accP[2 * d + 1], wE[16 + d], tql);
    }

    float res[8];
    #pragma unroll
    for (int dx = 0; dx < 8; dx++) {
        float2 p = *(float2*)&accP[dx];
        res[dx] = p.x + p.y;
    }

    float* o = out + ((size_t)(img * IMH + Y0 + r)) * IMW + X0 + ox;
    ((float4*)o)[0] = make_float4(res[0], res[1], res[2], res[3]);
    ((float4*)o)[1] = make_float4(res[4], res[5], res[6], res[7]);
}

// ---------------------------------------------------------------------------
extern "C" void kernel_launch(void* const* d_in, const int* in_sizes, int n_in,
                              void* d_out, int out_size) {
    const float* im   = (const float*)d_in[0];  // (16,3,512,512) f32
    const float* tmpl = (const float*)d_in[1];  // (16,3,32,32)  f32
    float* out = (float*)d_out;                 // (16,3,512,512) f32

    k_tnorm<<<NIMG, 256>>>(tmpl);
    k_hbox<0><<<NIMG * IMH / 8, 256>>>(im);                 // S1 horizontal
    k_vbox<0><<<NIMG * IMW * 4 / 256, 256>>>(im);           // im_c
    k_hbox<1><<<NIMG * IMH / 8, 256>>>(im);                 // S2 horizontal (imc^2)
    k_vbox<1><<<NIMG * IMW * 4 / 256, 256>>>(im);           // a = imc/energy
    k_conv<<<dim3(IMW / CTX, IMH / CTY, NIMG), 256>>>(out); // correlation
}